// round 4
// baseline (speedup 1.0000x reference)
#include <cuda_runtime.h>
#include <cuda_bf16.h>
#include <math.h>
#include <stdint.h>

#define BB 8
#define CC 64
#define NN 4096
#define HH 4
#define OO 128
#define KNN 20
#define PP (BB*NN)   // 32768

// ---------------- scratch (device globals; no allocs) ----------------
__device__ float g_pts[(size_t)PP*CC];        // (B,N,C) transposed x
__device__ float g_sq[PP];
__device__ int   g_idx[PP*KNN];
__device__ float g_M[HH*CC*CC];               // Wq^T Wk per head
__device__ float g_Wf[OO*HH*CC];              // Wout folded with Wv
__device__ float g_wd[(size_t)PP*HH*CC];      // weighted difference vectors
__device__ float g_y[(size_t)BB*OO*NN];       // pre-BN output
__device__ float g_mean[OO];
__device__ float g_istd[OO];
// bf16 hi/lo split, per 128-row tile: [tile][row][hi(32 words) | lo(32 words)]
__device__ unsigned int g_pack[(size_t)(PP/128)*8192];

// ---------------- warp MMA: m16n8k16 bf16 -> f32 ----------------
__device__ __forceinline__ void mma_bf16(float* d, const uint32_t* a, uint32_t b0, uint32_t b1) {
    asm volatile("mma.sync.aligned.m16n8k16.row.col.f32.bf16.bf16.f32 "
        "{%0,%1,%2,%3}, {%4,%5,%6,%7}, {%8,%9}, {%0,%1,%2,%3};"
        : "+f"(d[0]), "+f"(d[1]), "+f"(d[2]), "+f"(d[3])
        : "r"(a[0]), "r"(a[1]), "r"(a[2]), "r"(a[3]), "r"(b0), "r"(b1));
}

// ---------------- K0: transpose x -> pts ----------------
__global__ void k_transpose(const float* __restrict__ x) {
    __shared__ float tile[32][33];
    int b = blockIdx.z;
    int n0 = blockIdx.x * 32, c0 = blockIdx.y * 32;
    for (int i = threadIdx.y; i < 32; i += 8)
        tile[i][threadIdx.x] = x[((size_t)b*CC + c0 + i)*NN + n0 + threadIdx.x];
    __syncthreads();
    for (int i = threadIdx.y; i < 32; i += 8)
        g_pts[((size_t)b*NN + n0 + i)*CC + c0 + threadIdx.x] = tile[threadIdx.x][i];
}

// ---------------- K0b: copy x into out channels [128,192) ----------------
__global__ void k_copyx(const float* __restrict__ x, float* __restrict__ out) {
    size_t i = (size_t)blockIdx.x * blockDim.x + threadIdx.x;
    if (i >= (size_t)BB*CC*NN) return;
    int n = (int)(i & (NN-1));
    size_t t = i >> 12;
    int c = (int)(t & (CC-1));
    int b = (int)(t >> 6);
    out[((size_t)b*192 + 128 + c)*NN + n] = x[i];
}

// ---------------- K1: squared norms ----------------
__global__ void k_sqnorm() {
    int p = blockIdx.x * 8 + (threadIdx.x >> 5);
    int lane = threadIdx.x & 31;
    float v0 = g_pts[(size_t)p*64 + lane];
    float v1 = g_pts[(size_t)p*64 + 32 + lane];
    float s = v0*v0 + v1*v1;
    #pragma unroll
    for (int off = 16; off; off >>= 1) s += __shfl_xor_sync(0xFFFFFFFFu, s, off);
    if (lane == 0) g_sq[p] = s;
}

// ---------------- K1b: prepack bf16 hi/lo split ----------------
__global__ void k_prepack() {
    int w = threadIdx.x >> 5, l = threadIdx.x & 31;
    int p = blockIdx.x * 8 + w;
    float2 xv = ((const float2*)(g_pts + (size_t)p*64))[l];
    __nv_bfloat16 h0 = __float2bfloat16(xv.x);
    __nv_bfloat16 l0 = __float2bfloat16(xv.x - __bfloat162float(h0));
    __nv_bfloat16 h1 = __float2bfloat16(xv.y);
    __nv_bfloat16 l1 = __float2bfloat16(xv.y - __bfloat162float(h1));
    unsigned hh = ((unsigned)__bfloat16_as_ushort(h1) << 16) | (unsigned)__bfloat16_as_ushort(h0);
    unsigned ll = ((unsigned)__bfloat16_as_ushort(l1) << 16) | (unsigned)__bfloat16_as_ushort(l0);
    int tile = p >> 7, r = p & 127;
    size_t base = (size_t)tile*8192 + (size_t)r*64;
    g_pack[base + l]      = hh;
    g_pack[base + 32 + l] = ll;
}

// ---------------- K2: precompute M = Wq^T Wk per head ----------------
__global__ void k_precM(const float* __restrict__ Wq, const float* __restrict__ Wk) {
    int id = blockIdx.x * 256 + threadIdx.x;
    int cp = id & 63;
    int c  = (id >> 6) & 63;
    int h  = id >> 12;
    float acc = 0.f;
    #pragma unroll 8
    for (int e = 0; e < 64; e++)
        acc += Wq[(h*64 + e)*64 + c] * Wk[(h*64 + e)*64 + cp];
    g_M[id] = acc;
}

// ---------------- K2b: precompute Wf = Wout folded with Wv ----------------
__global__ void k_precWf(const float* __restrict__ Wout, const float* __restrict__ Wv) {
    int id = blockIdx.x * 256 + threadIdx.x;
    int c = id & 63;
    int h = (id >> 6) & 3;
    int o = id >> 8;
    float acc = 0.f;
    #pragma unroll 8
    for (int v = 0; v < 64; v++)
        acc += Wout[o*256 + h*64 + v] * Wv[(h*64 + v)*64 + c];
    g_Wf[id] = acc;
}

// ---------------- K3: fused MMA Gram + streaming top-21 ----------------
// Smem word layout:
//   As:   [0, 12800)      128 rows x 100 words (192 bf16 + pad)  A' = hi,lo,hi
//   Bs:   [12800, 25600)  same, B' = hi,hi,lo
//   Ds:   [25600, 42496)  128 x 132 floats
//   lval: [42496, 45184)  128*21 floats
//   lidx: [45184, 47872)  128*21 ints
//   sqb:  [47872, 48000)  128 floats
#define KNN_SMEM_BYTES 192000
__global__ void k_knn() {
    extern __shared__ unsigned int sm[];
    unsigned int* As = sm;
    unsigned int* Bs = sm + 12800;
    float* Ds   = (float*)(sm + 25600);
    float* lval = (float*)(sm + 42496);
    int*   lidx = (int*)  (sm + 45184);
    float* sqb  = (float*)(sm + 47872);

    int tid = threadIdx.x;
    int wid = tid >> 5, lane = tid & 31;
    int q = lane & 3, rg = lane >> 2;
    int b = blockIdx.y, it = blockIdx.x;

    // load A tile: segments hi, lo, hi
    {
        const uint4* src = ((const uint4*)g_pack) + (size_t)(b*32 + it)*2048;
        uint4* dst = (uint4*)As;
        for (int idx = tid; idx < 3072; idx += 256) {
            int seg = idx >> 10, rem = idx & 1023;
            int r = rem >> 3, u = rem & 7;
            int srcSeg = (seg == 1) ? 1 : 0;
            dst[r*25 + seg*8 + u] = src[r*16 + srcSeg*8 + u];
        }
    }

    float si = 0.f, thr = -3.402823466e38f;
    int cnt = 0, LB = tid*21;
    if (tid < 128) si = g_sq[b*4096 + it*128 + tid];

    int wm = (wid & 3) * 32;   // warp row base
    int wn = (wid >> 2) * 64;  // warp col base

    for (int tj = 0; tj < 32; tj++) {
        // load B tile: segments hi, hi, lo
        {
            const uint4* src = ((const uint4*)g_pack) + (size_t)(b*32 + tj)*2048;
            uint4* dst = (uint4*)Bs;
            for (int idx = tid; idx < 3072; idx += 256) {
                int seg = idx >> 10, rem = idx & 1023;
                int r = rem >> 3, u = rem & 7;
                int srcSeg = (seg == 2) ? 1 : 0;
                dst[r*25 + seg*8 + u] = src[r*16 + srcSeg*8 + u];
            }
        }
        if (tid < 128) sqb[tid] = g_sq[b*4096 + tj*128 + tid];
        __syncthreads();   // Bs ready; also orders prior scan before D overwrite

        // MMA: warp computes rows [wm, wm+32) x cols [wn, wn+64)
        float acc[16][4];
        #pragma unroll
        for (int i = 0; i < 16; i++)
            #pragma unroll
            for (int jj = 0; jj < 4; jj++) acc[i][jj] = 0.f;

        #pragma unroll
        for (int k = 0; k < 12; k++) {
            uint32_t af[2][4];
            #pragma unroll
            for (int mt = 0; mt < 2; mt++) {
                int rb = (wm + mt*16 + rg)*100 + k*8 + q;
                af[mt][0] = As[rb];
                af[mt][1] = As[rb + 800];
                af[mt][2] = As[rb + 4];
                af[mt][3] = As[rb + 804];
            }
            #pragma unroll
            for (int n = 0; n < 8; n++) {
                int bb = (wn + n*8 + rg)*100 + k*8 + q;
                uint32_t b0 = Bs[bb], b1 = Bs[bb + 4];
                mma_bf16(acc[n],     af[0], b0, b1);
                mma_bf16(acc[8 + n], af[1], b0, b1);
            }
        }

        // spill D tile
        #pragma unroll
        for (int mt = 0; mt < 2; mt++) {
            int r0 = wm + mt*16 + rg;
            #pragma unroll
            for (int n = 0; n < 8; n++) {
                int col = wn + n*8 + 2*q;
                *(float2*)&Ds[r0*132 + col]     = make_float2(acc[mt*8+n][0], acc[mt*8+n][1]);
                *(float2*)&Ds[(r0+8)*132 + col] = make_float2(acc[mt*8+n][2], acc[mt*8+n][3]);
            }
        }
        __syncthreads();

        // streaming top-21 scan (threads 0-127, one row each)
        if (tid < 128) {
            const float4* drow = (const float4*)&Ds[tid*132];
            int jb = tj*128;
            #pragma unroll 4
            for (int c4 = 0; c4 < 32; c4++) {
                float4 v4 = drow[c4];
                #pragma unroll
                for (int e = 0; e < 4; e++) {
                    float dot = (e == 0) ? v4.x : (e == 1) ? v4.y : (e == 2) ? v4.z : v4.w;
                    int j = c4*4 + e;
                    float d = 2.f*dot - si - sqb[j];
                    if (d > thr) {
                        int pos = (cnt < 21) ? cnt++ : 20;
                        while (pos > 0 && lval[LB + pos - 1] < d) {
                            lval[LB + pos] = lval[LB + pos - 1];
                            lidx[LB + pos] = lidx[LB + pos - 1];
                            pos--;
                        }
                        lval[LB + pos] = d;
                        lidx[LB + pos] = jb + j;
                        if (cnt == 21) thr = lval[LB + 20];
                    }
                }
            }
        }
        __syncthreads();
    }

    if (tid < 128) {
        int p = b*4096 + it*128 + tid;
        #pragma unroll
        for (int k = 0; k < 20; k++) g_idx[p*20 + k] = lidx[LB + 1 + k];
    }
}

// ---------------- K5: per-point attention -> weighted difference vectors ----------------
#define WPB 8
__global__ void k_attn() {
    __shared__ float nb[WPB][KNN][64];
    __shared__ float qs[WPB][64];
    __shared__ float tq[WPB][64];
    __shared__ float ps[WPB][KNN];
    __shared__ int   nbi[WPB][KNN];

    int w = threadIdx.x >> 5;
    int lane = threadIdx.x & 31;
    int p = blockIdx.x * WPB + w;
    int b = p >> 12;

    if (lane < KNN) nbi[w][lane] = g_idx[p * KNN + lane];
    float q0 = g_pts[(size_t)p*64 + lane];
    float q1 = g_pts[(size_t)p*64 + 32 + lane];
    qs[w][lane] = q0;
    qs[w][lane + 32] = q1;
    __syncwarp();
    #pragma unroll 4
    for (int k = 0; k < KNN; k++) {
        int j = nbi[w][k];
        const float* src = g_pts + ((size_t)(b << 12) + j)*64;
        nb[w][k][lane]      = src[lane];
        nb[w][k][lane + 32] = src[lane + 32];
    }
    __syncwarp();

    for (int h = 0; h < HH; h++) {
        const float* Mh = g_M + h * 4096;
        float t0 = 0.f, t1 = 0.f;
        #pragma unroll 8
        for (int c = 0; c < 64; c++) {
            float qc = qs[w][c];
            t0 += qc * __ldg(Mh + c*64 + lane);
            t1 += qc * __ldg(Mh + c*64 + 32 + lane);
        }
        tq[w][lane] = t0;
        tq[w][lane + 32] = t1;
        __syncwarp();

        float s = -3.402823466e38f;
        if (lane < KNN) {
            float acc = 0.f;
            #pragma unroll 8
            for (int c = 0; c < 64; c++) acc += tq[w][c] * nb[w][lane][c];
            s = acc * 0.125f;
        }
        float mx = s;
        #pragma unroll
        for (int off = 16; off; off >>= 1) mx = fmaxf(mx, __shfl_xor_sync(0xFFFFFFFFu, mx, off));
        float e = (lane < KNN) ? expf(s - mx) : 0.f;
        float sum = e;
        #pragma unroll
        for (int off = 16; off; off >>= 1) sum += __shfl_xor_sync(0xFFFFFFFFu, sum, off);
        if (lane < KNN) ps[w][lane] = e / sum;
        __syncwarp();

        float w0 = 0.f, w1 = 0.f;
        #pragma unroll 4
        for (int k = 0; k < KNN; k++) {
            float pk = ps[w][k];
            w0 += pk * (nb[w][k][lane]      - q0);
            w1 += pk * (nb[w][k][lane + 32] - q1);
        }
        g_wd[((size_t)p*HH + h)*64 + lane]      = w0;
        g_wd[((size_t)p*HH + h)*64 + 32 + lane] = w1;
        __syncwarp();
    }
}

// ---------------- K6: y = Wf (128x256) @ wd^T ----------------
__global__ void k_ygemm() {
    __shared__ float Wfs[32][129];
    __shared__ float wds[64][33];
    int tid = threadIdx.y * 16 + threadIdx.x;
    int p0 = blockIdx.x * 64;
    float acc[8][4] = {};

    for (int kt = 0; kt < 8; kt++) {
        for (int t = tid; t < 4096; t += 256) {
            int o = t >> 5, k = t & 31;
            Wfs[k][o] = g_Wf[o*256 + kt*32 + k];
        }
        for (int t = tid; t < 2048; t += 256) {
            int pp = t >> 5, k = t & 31;
            wds[pp][k] = g_wd[(size_t)(p0 + pp)*256 + kt*32 + k];
        }
        __syncthreads();
        #pragma unroll 8
        for (int k = 0; k < 32; k++) {
            float a[8], bb[4];
            #pragma unroll
            for (int ii = 0; ii < 8; ii++) a[ii] = Wfs[k][threadIdx.y*8 + ii];
            #pragma unroll
            for (int jj = 0; jj < 4; jj++) bb[jj] = wds[threadIdx.x*4 + jj][k];
            #pragma unroll
            for (int ii = 0; ii < 8; ii++)
                #pragma unroll
                for (int jj = 0; jj < 4; jj++)
                    acc[ii][jj] += a[ii] * bb[jj];
        }
        __syncthreads();
    }
    #pragma unroll
    for (int ii = 0; ii < 8; ii++) {
        int o = threadIdx.y*8 + ii;
        #pragma unroll
        for (int jj = 0; jj < 4; jj++) {
            int p = p0 + threadIdx.x*4 + jj;
            g_y[((size_t)(p >> 12)*OO + o)*NN + (p & 4095)] = acc[ii][jj];
        }
    }
}

// ---------------- K7: BN stats (double accumulation) ----------------
__global__ void k_bnstats() {
    __shared__ double rs[256], rss[256];
    int o = blockIdx.x;
    int tid = threadIdx.x;
    double s = 0.0, ss = 0.0;
    for (int b = 0; b < BB; b++) {
        const float* row = g_y + ((size_t)b*OO + o)*NN;
        for (int t = tid; t < NN; t += 256) {
            double v = (double)row[t];
            s += v; ss += v*v;
        }
    }
    rs[tid] = s; rss[tid] = ss;
    __syncthreads();
    for (int st = 128; st; st >>= 1) {
        if (tid < st) { rs[tid] += rs[tid + st]; rss[tid] += rss[tid + st]; }
        __syncthreads();
    }
    if (tid == 0) {
        double n = (double)(BB*NN);
        double mean = rs[0] / n;
        double var = rss[0] / n - mean*mean;
        g_mean[o] = (float)mean;
        g_istd[o] = (float)(1.0 / sqrt(var + 1e-5));
    }
}

// ---------------- K8: BN apply + LeakyReLU -> out channels [0,128) ----------------
__global__ void k_bnapply(const float* __restrict__ gamma, const float* __restrict__ beta,
                          float* __restrict__ out) {
    size_t i = (size_t)blockIdx.x * blockDim.x + threadIdx.x;
    if (i >= (size_t)BB*OO*NN) return;
    int n = (int)(i & (NN-1));
    size_t t = i >> 12;
    int o = (int)(t & (OO-1));
    int b = (int)(t >> 7);
    float v = (g_y[i] - g_mean[o]) * g_istd[o] * gamma[o] + beta[o];
    v = (v >= 0.f) ? v : 0.2f * v;
    out[((size_t)b*192 + o)*NN + n] = v;
}

// ---------------- launch ----------------
extern "C" void kernel_launch(void* const* d_in, const int* in_sizes, int n_in,
                              void* d_out, int out_size) {
    const float* x     = (const float*)d_in[0];
    const float* Wq    = (const float*)d_in[1];
    const float* Wk    = (const float*)d_in[2];
    const float* Wv    = (const float*)d_in[3];
    const float* Wout  = (const float*)d_in[4];
    const float* gamma = (const float*)d_in[5];
    const float* beta  = (const float*)d_in[6];
    float* out = (float*)d_out;

    cudaFuncSetAttribute(k_knn, cudaFuncAttributeMaxDynamicSharedMemorySize, KNN_SMEM_BYTES);

    k_transpose<<<dim3(NN/32, CC/32, BB), dim3(32, 8)>>>(x);
    k_copyx<<<(BB*CC*NN)/256, 256>>>(x, out);
    k_sqnorm<<<PP/8, 256>>>();
    k_prepack<<<PP/8, 256>>>();
    k_precM<<<64, 256>>>(Wq, Wk);
    k_precWf<<<128, 256>>>(Wout, Wv);
    k_knn<<<dim3(32, 8), 256, KNN_SMEM_BYTES>>>();
    k_attn<<<PP/WPB, 256>>>();
    k_ygemm<<<PP/64, dim3(16, 16)>>>();
    k_bnstats<<<OO, 256>>>();
    k_bnapply<<<(BB*OO*NN)/256, 256>>>(gamma, beta, out);
}